// round 1
// baseline (speedup 1.0000x reference)
#include <cuda_runtime.h>
#include <math.h>

#define TOKENS   8192
#define DM       1024
#define DFF      4096
#define NE       8
#define NSLOTS   (TOKENS * 2)

// ---------------- scratch (static device globals; no allocation) ----------------
__device__ __align__(16) float g_H[(size_t)NSLOTS * DFF];   // expert-grouped hidden acts
__device__ int   g_tope[NSLOTS];     // per-token top-2 expert ids (2 per token)
__device__ float g_topp[NSLOTS];     // per-token top-2 probs
__device__ int   g_tok[NSLOTS];      // slot -> token id (grouped by expert)
__device__ float g_gw[NSLOTS];       // slot -> gate weight
__device__ int   g_count[NE];
__device__ int   g_cursor[NE];
__device__ int   g_offset[NE + 1];

// ---------------- kernel 0: zero output + counters ----------------
__global__ void zero_kernel(float4* __restrict__ out) {
    const int gid = blockIdx.x * blockDim.x + threadIdx.x;
    const int stride = gridDim.x * blockDim.x;
    const int n4 = TOKENS * DM / 4;
    float4 z = make_float4(0.f, 0.f, 0.f, 0.f);
    for (int i = gid; i < n4; i += stride) out[i] = z;
    if (gid < NE) { g_count[gid] = 0; g_cursor[gid] = 0; }
}

// ---------------- kernel 1: gating (warp per token) ----------------
__global__ void __launch_bounds__(256) gate_kernel(
    const float* __restrict__ x,
    const float* __restrict__ gw,
    const float* __restrict__ gb)
{
    const int warp = (blockIdx.x * blockDim.x + threadIdx.x) >> 5;
    const int lane = threadIdx.x & 31;
    if (warp >= TOKENS) return;

    const float* xr = x + (size_t)warp * DM;
    float acc[NE];
#pragma unroll
    for (int e = 0; e < NE; e++) acc[e] = 0.f;

    for (int d = lane; d < DM; d += 32) {
        float xv = xr[d];
        const float4 g0 = *(const float4*)(gw + (size_t)d * NE);
        const float4 g1 = *(const float4*)(gw + (size_t)d * NE + 4);
        acc[0] += xv * g0.x;  acc[1] += xv * g0.y;
        acc[2] += xv * g0.z;  acc[3] += xv * g0.w;
        acc[4] += xv * g1.x;  acc[5] += xv * g1.y;
        acc[6] += xv * g1.z;  acc[7] += xv * g1.w;
    }
#pragma unroll
    for (int e = 0; e < NE; e++) {
#pragma unroll
        for (int off = 16; off; off >>= 1)
            acc[e] += __shfl_xor_sync(0xffffffffu, acc[e], off);
    }

    if (lane == 0) {
        float m = -1e30f;
#pragma unroll
        for (int e = 0; e < NE; e++) { acc[e] += gb[e]; m = fmaxf(m, acc[e]); }
        float s = 0.f;
#pragma unroll
        for (int e = 0; e < NE; e++) { acc[e] = __expf(acc[e] - m); s += acc[e]; }
        const float inv = 1.f / s;

        int i1 = 0; float p1 = acc[0];
#pragma unroll
        for (int e = 1; e < NE; e++) if (acc[e] > p1) { p1 = acc[e]; i1 = e; }
        int i2 = -1; float p2 = -1.f;
#pragma unroll
        for (int e = 0; e < NE; e++) if (e != i1 && acc[e] > p2) { p2 = acc[e]; i2 = e; }

        g_tope[2 * warp + 0] = i1;  g_topp[2 * warp + 0] = p1 * inv;
        g_tope[2 * warp + 1] = i2;  g_topp[2 * warp + 1] = p2 * inv;
        atomicAdd(&g_count[i1], 1);
        atomicAdd(&g_count[i2], 1);
    }
}

// ---------------- kernel 2: tiny scan ----------------
__global__ void scan_kernel() {
    int o = 0;
    g_offset[0] = 0;
    for (int e = 0; e < NE; e++) { o += g_count[e]; g_offset[e + 1] = o; }
}

// ---------------- kernel 3: scatter tokens into expert groups ----------------
__global__ void scatter_kernel() {
    const int t = blockIdx.x * blockDim.x + threadIdx.x;
    if (t >= TOKENS) return;
#pragma unroll
    for (int k = 0; k < 2; k++) {
        const int e = g_tope[2 * t + k];
        const float p = g_topp[2 * t + k];
        const int pos = g_offset[e] + atomicAdd(&g_cursor[e], 1);
        g_tok[pos] = t;
        g_gw[pos] = p;
    }
}

// ---------------- kernel 4: GEMM1 (gathered x @ w1[e]) + bias + SiLU -> H ----------------
// BM=BN=128, BK=8, 256 threads, 8x8 per thread.
__global__ void __launch_bounds__(256) gemm1_kernel(
    const float* __restrict__ x,
    const float* __restrict__ w1,
    const float* __restrict__ b1)
{
    const int e = blockIdx.z;
    const int cnt = g_count[e];
    const int rowStart = blockIdx.y * 128;
    if (rowStart >= cnt) return;
    const int base = g_offset[e];
    const int n0 = blockIdx.x * 128;

    const float* B = w1 + (size_t)e * DM * DFF;

    __shared__ float As[8][128];
    __shared__ float Bs[8][128];

    const int tid = threadIdx.x;
    const int tm = tid >> 4;          // 0..15
    const int tn = tid & 15;          // 0..15

    // A load mapping: one float4 per thread
    const int ar = tid >> 1;          // 0..127
    const int ac = (tid & 1) * 4;     // 0 or 4
    const int arow = rowStart + ar;
    const bool aok = arow < cnt;
    const int tok = aok ? g_tok[base + arow] : 0;
    const float* Aptr = x + (size_t)tok * DM + ac;

    // B load mapping: one float4 per thread
    const int bk = tid >> 5;          // 0..7
    const int bn = (tid & 31) * 4;    // 0..124
    const float* Bptr = B + (size_t)bk * DFF + n0 + bn;

    float acc[8][8];
#pragma unroll
    for (int i = 0; i < 8; i++)
#pragma unroll
        for (int j = 0; j < 8; j++) acc[i][j] = 0.f;

    for (int k0 = 0; k0 < DM; k0 += 8) {
        const float4 av = *(const float4*)(Aptr + k0);
        As[ac + 0][ar] = av.x;
        As[ac + 1][ar] = av.y;
        As[ac + 2][ar] = av.z;
        As[ac + 3][ar] = av.w;
        *(float4*)&Bs[bk][bn] = *(const float4*)(Bptr + (size_t)k0 * DFF);
        __syncthreads();
#pragma unroll
        for (int k = 0; k < 8; k++) {
            float a[8], b[8];
            *(float4*)&a[0] = *(const float4*)&As[k][tm * 8];
            *(float4*)&a[4] = *(const float4*)&As[k][tm * 8 + 4];
            *(float4*)&b[0] = *(const float4*)&Bs[k][tn * 8];
            *(float4*)&b[4] = *(const float4*)&Bs[k][tn * 8 + 4];
#pragma unroll
            for (int i = 0; i < 8; i++)
#pragma unroll
                for (int j = 0; j < 8; j++) acc[i][j] += a[i] * b[j];
        }
        __syncthreads();
    }

    // epilogue: bias + SiLU, store to H
    float bb[8];
#pragma unroll
    for (int j = 0; j < 8; j++) bb[j] = b1[(size_t)e * DFF + n0 + tn * 8 + j];

#pragma unroll
    for (int i = 0; i < 8; i++) {
        const int r = tm * 8 + i;
        if (rowStart + r < cnt) {
            const int slot = base + rowStart + r;
            float v[8];
#pragma unroll
            for (int j = 0; j < 8; j++) {
                const float h = acc[i][j] + bb[j];
                v[j] = h / (1.f + __expf(-h));   // SiLU
            }
            float* hp = &g_H[(size_t)slot * DFF + n0 + tn * 8];
            *(float4*)(hp)     = *(float4*)&v[0];
            *(float4*)(hp + 4) = *(float4*)&v[4];
        }
    }
}

// ---------------- kernel 5: GEMM2 (H @ w2[e]) + bias, gated scatter-add ----------------
__global__ void __launch_bounds__(256) gemm2_kernel(
    const float* __restrict__ w2,
    const float* __restrict__ b2,
    float* __restrict__ out)
{
    const int e = blockIdx.z;
    const int cnt = g_count[e];
    const int rowStart = blockIdx.y * 128;
    if (rowStart >= cnt) return;
    const int base = g_offset[e];
    const int n0 = blockIdx.x * 128;

    const float* B = w2 + (size_t)e * DFF * DM;

    __shared__ float As[8][128];
    __shared__ float Bs[8][128];

    const int tid = threadIdx.x;
    const int tm = tid >> 4;
    const int tn = tid & 15;

    const int ar = tid >> 1;
    const int ac = (tid & 1) * 4;
    const int arow = rowStart + ar;
    const bool aok = arow < cnt;
    const float* Aptr = g_H + (size_t)(base + arow) * DFF + ac;

    const int bk = tid >> 5;
    const int bn = (tid & 31) * 4;
    const float* Bptr = B + (size_t)bk * DM + n0 + bn;

    float acc[8][8];
#pragma unroll
    for (int i = 0; i < 8; i++)
#pragma unroll
        for (int j = 0; j < 8; j++) acc[i][j] = 0.f;

    const float4 z4 = make_float4(0.f, 0.f, 0.f, 0.f);
    for (int k0 = 0; k0 < DFF; k0 += 8) {
        const float4 av = aok ? *(const float4*)(Aptr + k0) : z4;
        As[ac + 0][ar] = av.x;
        As[ac + 1][ar] = av.y;
        As[ac + 2][ar] = av.z;
        As[ac + 3][ar] = av.w;
        *(float4*)&Bs[bk][bn] = *(const float4*)(Bptr + (size_t)k0 * DM);
        __syncthreads();
#pragma unroll
        for (int k = 0; k < 8; k++) {
            float a[8], b[8];
            *(float4*)&a[0] = *(const float4*)&As[k][tm * 8];
            *(float4*)&a[4] = *(const float4*)&As[k][tm * 8 + 4];
            *(float4*)&b[0] = *(const float4*)&Bs[k][tn * 8];
            *(float4*)&b[4] = *(const float4*)&Bs[k][tn * 8 + 4];
#pragma unroll
            for (int i = 0; i < 8; i++)
#pragma unroll
                for (int j = 0; j < 8; j++) acc[i][j] += a[i] * b[j];
        }
        __syncthreads();
    }

    float bb[8];
#pragma unroll
    for (int j = 0; j < 8; j++) bb[j] = b2[(size_t)e * DM + n0 + tn * 8 + j];

#pragma unroll
    for (int i = 0; i < 8; i++) {
        const int r = tm * 8 + i;
        if (rowStart + r < cnt) {
            const int slot = base + rowStart + r;
            const int tokid = g_tok[slot];
            const float gwv = g_gw[slot];
            float* op = out + (size_t)tokid * DM + n0 + tn * 8;
#pragma unroll
            for (int j = 0; j < 8; j++) {
                atomicAdd(op + j, gwv * (acc[i][j] + bb[j]));
            }
        }
    }
}

// ---------------- launch ----------------
extern "C" void kernel_launch(void* const* d_in, const int* in_sizes, int n_in,
                              void* d_out, int out_size)
{
    const float* x      = (const float*)d_in[0];
    const float* gate_w = (const float*)d_in[1];
    const float* gate_b = (const float*)d_in[2];
    const float* w1     = (const float*)d_in[3];
    const float* b1     = (const float*)d_in[4];
    const float* w2     = (const float*)d_in[5];
    const float* b2     = (const float*)d_in[6];
    float* out = (float*)d_out;

    zero_kernel<<<2048, 256>>>((float4*)out);
    gate_kernel<<<TOKENS / 8, 256>>>(x, gate_w, gate_b);
    scan_kernel<<<1, 1>>>();
    scatter_kernel<<<TOKENS / 256, 256>>>();

    dim3 g1(DFF / 128, 64, NE);   // 32 x 64 x 8 (excess row tiles early-exit)
    gemm1_kernel<<<g1, 256>>>(x, w1, b1);

    dim3 g2(DM / 128, 64, NE);    // 8 x 64 x 8
    gemm2_kernel<<<g2, 256>>>(w2, b2, out);
}

// round 3
// speedup vs baseline: 2.1801x; 2.1801x over previous
#include <cuda_runtime.h>
#include <cuda_fp16.h>
#include <cstdint>
#include <math.h>

#define TOKENS   8192
#define DM       1024
#define DFF      4096
#define NE       8
#define NSLOTS   (TOKENS * 2)

#define BM       128
#define BN       128
#define KC       32              // halves per K chunk
#define STAGES   3
#define ROWB     80              // smem row stride bytes (32 halves + 16B pad)
#define TILEB    (128 * ROWB)    // 10240 B per A or B tile
#define STAGE_B  (2 * TILEB)     // A+B per stage
#define SMEM_DYN (STAGES * STAGE_B)

// ---------------- static device scratch ----------------
__device__ __align__(16) __half g_xhi[(size_t)TOKENS * DM];
__device__ __align__(16) __half g_xlo[(size_t)TOKENS * DM];
__device__ __align__(16) __half g_w1t_hi[(size_t)NE * DFF * DM];   // [E][N=DFF][K=DM]
__device__ __align__(16) __half g_w1t_lo[(size_t)NE * DFF * DM];
__device__ __align__(16) __half g_w2t_hi[(size_t)NE * DM * DFF];   // [E][N=DM][K=DFF]
__device__ __align__(16) __half g_w2t_lo[(size_t)NE * DM * DFF];
__device__ __align__(16) __half g_Hhi[(size_t)NSLOTS * DFF];
__device__ __align__(16) __half g_Hlo[(size_t)NSLOTS * DFF];
__device__ int   g_tope[NSLOTS];
__device__ float g_topp[NSLOTS];
__device__ int   g_tok[NSLOTS];
__device__ float g_gw[NSLOTS];
__device__ int   g_count[NE];
__device__ int   g_cursor[NE];
__device__ int   g_offset[NE + 1];

// ---------------- PTX helpers (sm_80-level only) ----------------
__device__ __forceinline__ uint32_t smem_u32(const void* p) {
    uint32_t a;
    asm("{ .reg .u64 t; cvta.to.shared.u64 t, %1; cvt.u32.u64 %0, t; }" : "=r"(a) : "l"(p));
    return a;
}
__device__ __forceinline__ void cp_async16(uint32_t dst, const void* src) {
    asm volatile("cp.async.cg.shared.global [%0], [%1], 16;" :: "r"(dst), "l"(src) : "memory");
}
__device__ __forceinline__ void cp_commit() {
    asm volatile("cp.async.commit_group;" ::: "memory");
}
template<int N>
__device__ __forceinline__ void cp_wait() {
    asm volatile("cp.async.wait_group %0;" :: "n"(N) : "memory");
}
__device__ __forceinline__ void ldm_x4(uint32_t* r, uint32_t addr) {
    asm volatile("ldmatrix.sync.aligned.m8n8.x4.shared.b16 {%0,%1,%2,%3}, [%4];"
                 : "=r"(r[0]), "=r"(r[1]), "=r"(r[2]), "=r"(r[3]) : "r"(addr));
}
__device__ __forceinline__ void ldm_x2(uint32_t* r, uint32_t addr) {
    asm volatile("ldmatrix.sync.aligned.m8n8.x2.shared.b16 {%0,%1}, [%2];"
                 : "=r"(r[0]), "=r"(r[1]) : "r"(addr));
}
__device__ __forceinline__ void mma_f16(float* c, const uint32_t* a, const uint32_t* b) {
    asm volatile(
        "mma.sync.aligned.m16n8k16.row.col.f32.f16.f16.f32 "
        "{%0,%1,%2,%3}, {%4,%5,%6,%7}, {%8,%9}, {%0,%1,%2,%3};"
        : "+f"(c[0]), "+f"(c[1]), "+f"(c[2]), "+f"(c[3])
        : "r"(a[0]), "r"(a[1]), "r"(a[2]), "r"(a[3]), "r"(b[0]), "r"(b[1]));
}

// ---------------- kernel 0: zero output + counters ----------------
__global__ void zero_kernel(float4* __restrict__ out) {
    const int gid = blockIdx.x * blockDim.x + threadIdx.x;
    const int stride = gridDim.x * blockDim.x;
    const int n4 = TOKENS * DM / 4;
    float4 z = make_float4(0.f, 0.f, 0.f, 0.f);
    for (int i = gid; i < n4; i += stride) out[i] = z;
    if (gid < NE) { g_count[gid] = 0; g_cursor[gid] = 0; }
}

// ---------------- kernel 1: gating (warp per token) ----------------
__global__ void __launch_bounds__(256) gate_kernel(
    const float* __restrict__ x, const float* __restrict__ gw, const float* __restrict__ gb)
{
    const int warp = (blockIdx.x * blockDim.x + threadIdx.x) >> 5;
    const int lane = threadIdx.x & 31;
    if (warp >= TOKENS) return;

    const float* xr = x + (size_t)warp * DM;
    float acc[NE];
#pragma unroll
    for (int e = 0; e < NE; e++) acc[e] = 0.f;
    for (int d = lane; d < DM; d += 32) {
        float xv = xr[d];
        const float4 g0 = *(const float4*)(gw + (size_t)d * NE);
        const float4 g1 = *(const float4*)(gw + (size_t)d * NE + 4);
        acc[0] += xv * g0.x;  acc[1] += xv * g0.y;
        acc[2] += xv * g0.z;  acc[3] += xv * g0.w;
        acc[4] += xv * g1.x;  acc[5] += xv * g1.y;
        acc[6] += xv * g1.z;  acc[7] += xv * g1.w;
    }
#pragma unroll
    for (int e = 0; e < NE; e++) {
#pragma unroll
        for (int off = 16; off; off >>= 1)
            acc[e] += __shfl_xor_sync(0xffffffffu, acc[e], off);
    }
    if (lane == 0) {
        float m = -1e30f;
#pragma unroll
        for (int e = 0; e < NE; e++) { acc[e] += gb[e]; m = fmaxf(m, acc[e]); }
        float s = 0.f;
#pragma unroll
        for (int e = 0; e < NE; e++) { acc[e] = __expf(acc[e] - m); s += acc[e]; }
        const float inv = 1.f / s;
        int i1 = 0; float p1 = acc[0];
#pragma unroll
        for (int e = 1; e < NE; e++) if (acc[e] > p1) { p1 = acc[e]; i1 = e; }
        int i2 = -1; float p2 = -1.f;
#pragma unroll
        for (int e = 0; e < NE; e++) if (e != i1 && acc[e] > p2) { p2 = acc[e]; i2 = e; }
        g_tope[2 * warp + 0] = i1;  g_topp[2 * warp + 0] = p1 * inv;
        g_tope[2 * warp + 1] = i2;  g_topp[2 * warp + 1] = p2 * inv;
        atomicAdd(&g_count[i1], 1);
        atomicAdd(&g_count[i2], 1);
    }
}

// ---------------- kernel 2/3: scan + scatter ----------------
__global__ void scan_kernel() {
    int o = 0;
    g_offset[0] = 0;
    for (int e = 0; e < NE; e++) { o += g_count[e]; g_offset[e + 1] = o; }
}
__global__ void scatter_kernel() {
    const int t = blockIdx.x * blockDim.x + threadIdx.x;
    if (t >= TOKENS) return;
#pragma unroll
    for (int k = 0; k < 2; k++) {
        const int e = g_tope[2 * t + k];
        const float p = g_topp[2 * t + k];
        const int pos = g_offset[e] + atomicAdd(&g_cursor[e], 1);
        g_tok[pos] = t;
        g_gw[pos] = p;
    }
}

// ---------------- preprocess: decompose x into fp16 hi/lo ----------------
__global__ void decomp_x_kernel(const float* __restrict__ x) {
    const int gid = blockIdx.x * blockDim.x + threadIdx.x;
    const int stride = gridDim.x * blockDim.x;
    const int n = TOKENS * DM;
    for (int i = gid; i < n; i += stride) {
        const float v = x[i];
        const __half h = __float2half_rn(v);
        g_xhi[i] = h;
        g_xlo[i] = __float2half_rn(v - __half2float(h));
    }
}

// ---------------- preprocess: transpose [E][K][N] -> [E][N][K] + fp16 decompose ----------------
template<int K, int N>
__global__ void __launch_bounds__(256) transpose_decomp_kernel(
    const float* __restrict__ w, __half* __restrict__ ohi, __half* __restrict__ olo)
{
    __shared__ float t[32][33];
    const int e = blockIdx.z;
    const float* in = w + (size_t)e * K * N;
    __half* oh = ohi + (size_t)e * N * K;
    __half* ol = olo + (size_t)e * N * K;

    const int n = blockIdx.x * 32 + threadIdx.x;
#pragma unroll
    for (int i = 0; i < 4; i++) {
        const int k = blockIdx.y * 32 + threadIdx.y + i * 8;
        t[threadIdx.y + i * 8][threadIdx.x] = in[(size_t)k * N + n];
    }
    __syncthreads();
    const int k2 = blockIdx.y * 32 + threadIdx.x;
#pragma unroll
    for (int i = 0; i < 4; i++) {
        const int n2 = blockIdx.x * 32 + threadIdx.y + i * 8;
        const float v = t[threadIdx.x][threadIdx.y + i * 8];
        const __half h = __float2half_rn(v);
        oh[(size_t)n2 * K + k2] = h;
        ol[(size_t)n2 * K + k2] = __float2half_rn(v - __half2float(h));
    }
}

// ---------------- fp16 mma.sync GEMM, 3-term fp32 emulation via K-concat ----------------
// A chunks: [hi | hi | lo], B chunks: [hi | lo | hi] => hi*hi + hi*lo + lo*hi
// CTA 128x128, BK=32 halves, 3-stage cp.async pipeline, 8 warps (2 x 4).
template<int KDIM, int NDIM, bool G1>
__global__ void __launch_bounds__(256) moe_gemm(
    const __half* __restrict__ Ahi, const __half* __restrict__ Alo,
    const __half* __restrict__ Bhi, const __half* __restrict__ Blo,
    const float* __restrict__ bias,
    __half* __restrict__ oHhi, __half* __restrict__ oHlo,   // G1 outputs
    float* __restrict__ out)                                // G2 output
{
    const int e = blockIdx.z;
    const int cnt = g_count[e];
    const int rowStart = blockIdx.x * BM;
    if (rowStart >= cnt) return;
    const int base = g_offset[e];
    const int n0 = blockIdx.y * BN;

    extern __shared__ __align__(128) char smem[];
    const uint32_t SB_ = smem_u32(smem);

    const int tid  = threadIdx.x;
    const int warp = tid >> 5;
    const int lane = tid & 31;
    const int warpM = warp & 1;       // 2 warp rows (64 each)
    const int warpN = warp >> 1;      // 4 warp cols (32 each)
    const int m0 = warpM * 64;
    const int nw0 = warpN * 32;

    constexpr int KCPK = KDIM / KC;
    constexpr int NC   = 3 * KCPK;

    // ---- per-thread cp.async source row offsets (elements) ----
    const int lrow = tid >> 2;        // 0..63
    const int segB = (tid & 3) * 16;  // smem byte offset within row
    const int segE = (tid & 3) * 8;   // element offset within K chunk

    size_t aoff0, aoff1;
    if (G1) {
        const int t0 = g_tok[base + min(rowStart + lrow,      cnt - 1)];
        const int t1 = g_tok[base + min(rowStart + lrow + 64, cnt - 1)];
        aoff0 = (size_t)t0 * KDIM;
        aoff1 = (size_t)t1 * KDIM;
    } else {
        aoff0 = (size_t)(base + min(rowStart + lrow,      cnt - 1)) * KDIM;
        aoff1 = (size_t)(base + min(rowStart + lrow + 64, cnt - 1)) * KDIM;
    }
    const size_t boff0 = ((size_t)e * NDIM + n0 + lrow)      * KDIM;
    const size_t boff1 = ((size_t)e * NDIM + n0 + lrow + 64) * KDIM;

    auto load_chunk = [&](int c) {
        const int s  = c % STAGES;
        const int p  = c / KCPK;
        const int kk = (c - p * KCPK) * KC;
        const __half* As = (p < 2)  ? Ahi : Alo;
        const __half* Bs = (p == 1) ? Blo : Bhi;
        const uint32_t da = SB_ + s * STAGE_B;
        const uint32_t db = da + TILEB;
        cp_async16(da + (uint32_t)lrow * ROWB + segB,        As + aoff0 + kk + segE);
        cp_async16(da + (uint32_t)(lrow + 64) * ROWB + segB, As + aoff1 + kk + segE);
        cp_async16(db + (uint32_t)lrow * ROWB + segB,        Bs + boff0 + kk + segE);
        cp_async16(db + (uint32_t)(lrow + 64) * ROWB + segB, Bs + boff1 + kk + segE);
        cp_commit();
    };

    float acc[4][4][4];
#pragma unroll
    for (int i = 0; i < 4; i++)
#pragma unroll
        for (int j = 0; j < 4; j++)
#pragma unroll
            for (int k = 0; k < 4; k++) acc[i][j][k] = 0.f;

    // prologue: fill STAGES-1 stages
    load_chunk(0);
    load_chunk(1);

    // precomputed ldmatrix smem offsets (within a stage)
    const uint32_t aRowOff = (uint32_t)(m0 + (lane & 15)) * ROWB + (lane >> 4) * 16;
    const uint32_t bRowOff = (uint32_t)(nw0 + (lane & 7)) * ROWB + ((lane >> 3) & 1) * 16;

    for (int c = 0; c < NC; c++) {
        cp_wait<1>();
        __syncthreads();
        if (c + 2 < NC) load_chunk(c + 2); else cp_commit();

        const int s = c % STAGES;
        const uint32_t da = SB_ + s * STAGE_B;
        const uint32_t db = da + TILEB;

#pragma unroll
        for (int ks = 0; ks < 2; ks++) {           // two k16 steps per chunk
            uint32_t bfr[4][2];
#pragma unroll
            for (int ni = 0; ni < 4; ni++)
                ldm_x2(bfr[ni], db + bRowOff + ni * 8 * ROWB + ks * 32);
            uint32_t afr[4][4];
#pragma unroll
            for (int mi = 0; mi < 4; mi++)
                ldm_x4(afr[mi], da + aRowOff + mi * 16 * ROWB + ks * 32);
#pragma unroll
            for (int mi = 0; mi < 4; mi++)
#pragma unroll
                for (int ni = 0; ni < 4; ni++)
                    mma_f16(acc[mi][ni], afr[mi], bfr[ni]);
        }
    }
    cp_wait<0>();

    // ---- epilogue ----
    const int gl = lane >> 2;
    const int tl = lane & 3;
#pragma unroll
    for (int mi = 0; mi < 4; mi++) {
        const int r0 = rowStart + m0 + mi * 16 + gl;
        const int r1 = r0 + 8;
#pragma unroll
        for (int ni = 0; ni < 4; ni++) {
            const int col = n0 + nw0 + ni * 8 + tl * 2;
            const float bv0 = bias[(size_t)e * NDIM + col];
            const float bv1 = bias[(size_t)e * NDIM + col + 1];
            if (G1) {
#pragma unroll
                for (int h = 0; h < 2; h++) {
                    const int r = h ? r1 : r0;
                    if (r < cnt) {
                        const int slot = base + r;
                        const float v0 = acc[mi][ni][2 * h + 0] + bv0;
                        const float v1 = acc[mi][ni][2 * h + 1] + bv1;
                        const float s0 = v0 / (1.f + __expf(-v0));
                        const float s1 = v1 / (1.f + __expf(-v1));
                        const __half h0 = __float2half_rn(s0);
                        const __half h1 = __float2half_rn(s1);
                        const __half l0 = __float2half_rn(s0 - __half2float(h0));
                        const __half l1 = __float2half_rn(s1 - __half2float(h1));
                        *(__half2*)(oHhi + (size_t)slot * NDIM + col) = __halves2half2(h0, h1);
                        *(__half2*)(oHlo + (size_t)slot * NDIM + col) = __halves2half2(l0, l1);
                    }
                }
            } else {
#pragma unroll
                for (int h = 0; h < 2; h++) {
                    const int r = h ? r1 : r0;
                    if (r < cnt) {
                        const int slot = base + r;
                        const int tk = g_tok[slot];
                        const float gwv = g_gw[slot];
                        float* op = out + (size_t)tk * DM + col;
                        atomicAdd(op,     gwv * (acc[mi][ni][2 * h + 0] + bv0));
                        atomicAdd(op + 1, gwv * (acc[mi][ni][2 * h + 1] + bv1));
                    }
                }
            }
        }
    }
}

// ---------------- launch ----------------
extern "C" void kernel_launch(void* const* d_in, const int* in_sizes, int n_in,
                              void* d_out, int out_size)
{
    const float* x      = (const float*)d_in[0];
    const float* gate_w = (const float*)d_in[1];
    const float* gate_b = (const float*)d_in[2];
    const float* w1     = (const float*)d_in[3];
    const float* b1     = (const float*)d_in[4];
    const float* w2     = (const float*)d_in[5];
    const float* b2     = (const float*)d_in[6];
    float* out = (float*)d_out;

    cudaFuncSetAttribute(moe_gemm<DM, DFF, true>,
                         cudaFuncAttributeMaxDynamicSharedMemorySize, SMEM_DYN);
    cudaFuncSetAttribute(moe_gemm<DFF, DM, false>,
                         cudaFuncAttributeMaxDynamicSharedMemorySize, SMEM_DYN);

    __half *xhi, *xlo, *w1thi, *w1tlo, *w2thi, *w2tlo, *Hhi, *Hlo;
    cudaGetSymbolAddress((void**)&xhi,   g_xhi);
    cudaGetSymbolAddress((void**)&xlo,   g_xlo);
    cudaGetSymbolAddress((void**)&w1thi, g_w1t_hi);
    cudaGetSymbolAddress((void**)&w1tlo, g_w1t_lo);
    cudaGetSymbolAddress((void**)&w2thi, g_w2t_hi);
    cudaGetSymbolAddress((void**)&w2tlo, g_w2t_lo);
    cudaGetSymbolAddress((void**)&Hhi,   g_Hhi);
    cudaGetSymbolAddress((void**)&Hlo,   g_Hlo);

    zero_kernel<<<2048, 256>>>((float4*)out);
    gate_kernel<<<TOKENS / 8, 256>>>(x, gate_w, gate_b);
    scan_kernel<<<1, 1>>>();
    scatter_kernel<<<TOKENS / 256, 256>>>();

    decomp_x_kernel<<<2048, 256>>>(x);
    {
        dim3 g(DFF / 32, DM / 32, NE);
        transpose_decomp_kernel<DM, DFF><<<g, dim3(32, 8)>>>(w1, w1thi, w1tlo);
    }
    {
        dim3 g(DM / 32, DFF / 32, NE);
        transpose_decomp_kernel<DFF, DM><<<g, dim3(32, 8)>>>(w2, w2thi, w2tlo);
    }

    {
        dim3 g(NSLOTS / BM, DFF / BN, NE);   // (128, 32, 8); excess M tiles exit fast
        moe_gemm<DM, DFF, true><<<g, 256, SMEM_DYN>>>(
            xhi, xlo, w1thi, w1tlo, b1, Hhi, Hlo, nullptr);
    }
    {
        dim3 g(NSLOTS / BM, DM / BN, NE);    // (128, 8, 8)
        moe_gemm<DFF, DM, false><<<g, 256, SMEM_DYN>>>(
            Hhi, Hlo, w2thi, w2tlo, b2, nullptr, nullptr, out);
    }
}

// round 7
// speedup vs baseline: 3.1683x; 1.4533x over previous
#include <cuda_runtime.h>
#include <cuda_fp16.h>
#include <cstdint>
#include <math.h>

#define TOKENS   8192
#define DM       1024
#define DFF      4096
#define NE       8
#define NSLOTS   (TOKENS * 2)

#define MT_MAX   (NSLOTS / 128 + NE)   // 136 padded m-tiles max
#define PADSLOTS (MT_MAX * 128)        // 17408
#define KCH1     (DM / 32)             // 32 k-chunks for GEMM1
#define KCH2     (DFF / 32)            // 128 k-chunks for GEMM2
#define NT1      (DFF / 128)           // 32 n-tiles GEMM1
#define NT2      (DM / 128)            // 8  n-tiles GEMM2

#define STAGES   3
#define STAGE_B  32768                 // A_hi + A_lo + B_hi + B_lo (4 x 8KB)
#define SMEM_DYN (STAGES * STAGE_B + 64)

// ---------------- static device scratch (fragment-linear tiled) ----------------
__device__ __align__(16) __half g_A1hi[(size_t)PADSLOTS * DM];
__device__ __align__(16) __half g_A1lo[(size_t)PADSLOTS * DM];
__device__ __align__(16) __half g_B1hi[(size_t)NE * DFF * DM];
__device__ __align__(16) __half g_B1lo[(size_t)NE * DFF * DM];
__device__ __align__(16) __half g_Hhi[(size_t)PADSLOTS * DFF];
__device__ __align__(16) __half g_Hlo[(size_t)PADSLOTS * DFF];
__device__ __align__(16) __half g_B2hi[(size_t)NE * DM * DFF];
__device__ __align__(16) __half g_B2lo[(size_t)NE * DM * DFF];

__device__ int   g_tope[NSLOTS];
__device__ float g_topp[NSLOTS];
__device__ int   g_tok_pad[PADSLOTS];
__device__ float g_gw_pad[PADSLOTS];
__device__ int   g_count[NE];
__device__ int   g_cursor[NE];
__device__ int   g_offpad[NE];
__device__ int   g_mt_e[MT_MAX];
__device__ int   g_mt_valid[MT_MAX];
__device__ int   g_nmt;

struct alignas(16) H8 { __half h[8]; };

// ---------------- PTX helpers ----------------
__device__ __forceinline__ uint32_t smem_u32(const void* p) {
    uint32_t a;
    asm("{ .reg .u64 t; cvta.to.shared.u64 t, %1; cvt.u32.u64 %0, t; }" : "=r"(a) : "l"(p));
    return a;
}
#define MBAR_INIT(a, c) \
    asm volatile("mbarrier.init.shared.b64 [%0], %1;" :: "r"(a), "r"((uint32_t)(c)) : "memory")
#define MBAR_EXPECT_TX(a, b) \
    asm volatile("mbarrier.arrive.expect_tx.shared.b64 _, [%0], %1;" :: "r"(a), "r"((uint32_t)(b)) : "memory")
#define MBAR_ARRIVE(a) \
    asm volatile("mbarrier.arrive.shared.b64 _, [%0];" :: "r"(a) : "memory")

__device__ __forceinline__ void mbar_wait(uint32_t mbar, uint32_t parity) {
    asm volatile(
        "{\n\t.reg .pred P;\n"
        "WL_%=:\n\t"
        "mbarrier.try_wait.parity.acquire.cta.shared::cta.b64 P, [%0], %1, 0x989680;\n\t"
        "@P bra.uni WD_%=;\n\t"
        "bra.uni WL_%=;\n"
        "WD_%=:\n\t}"
        :: "r"(mbar), "r"(parity) : "memory");
}
__device__ __forceinline__ void mbar_wait_relaxed(uint32_t mbar, uint32_t parity) {
    asm volatile(
        "{\n\t.reg .pred P;\n"
        "WL_%=:\n\t"
        "mbarrier.try_wait.parity.relaxed.cta.shared::cta.b64 P, [%0], %1, 0x989680;\n\t"
        "@P bra.uni WD_%=;\n\t"
        "bra.uni WL_%=;\n"
        "WD_%=:\n\t}"
        :: "r"(mbar), "r"(parity) : "memory");
}
__device__ __forceinline__ void bulk_g2s(uint32_t dst, const void* src, uint32_t bytes, uint32_t mbar) {
    asm volatile(
        "cp.async.bulk.shared::cluster.global.mbarrier::complete_tx::bytes [%0], [%1], %2, [%3];"
        :: "r"(dst), "l"(src), "r"(bytes), "r"(mbar) : "memory");
}
__device__ __forceinline__ uint4 lds128(uint32_t a) {
    uint4 v;
    asm volatile("ld.shared.v4.u32 {%0,%1,%2,%3}, [%4];"
                 : "=r"(v.x), "=r"(v.y), "=r"(v.z), "=r"(v.w) : "r"(a));
    return v;
}
__device__ __forceinline__ void mma_f16(float* c, const uint32_t* a, uint32_t b0, uint32_t b1) {
    asm volatile(
        "mma.sync.aligned.m16n8k16.row.col.f32.f16.f16.f32 "
        "{%0,%1,%2,%3}, {%4,%5,%6,%7}, {%8,%9}, {%0,%1,%2,%3};"
        : "+f"(c[0]), "+f"(c[1]), "+f"(c[2]), "+f"(c[3])
        : "r"(a[0]), "r"(a[1]), "r"(a[2]), "r"(a[3]), "r"(b0), "r"(b1));
}
__device__ __forceinline__ uint32_t pack_h2(__half a, __half b) {
    __half2 h = __halves2half2(a, b);
    return *(uint32_t*)&h;
}

// ---------------- kernel 0: zero output + routing state ----------------
__global__ void zero_kernel(float4* __restrict__ out) {
    const int gid = blockIdx.x * blockDim.x + threadIdx.x;
    const int stride = gridDim.x * blockDim.x;
    const int n4 = TOKENS * DM / 4;
    float4 z = make_float4(0.f, 0.f, 0.f, 0.f);
    for (int i = gid; i < n4; i += stride) out[i] = z;
    if (gid < PADSLOTS) g_tok_pad[gid] = -1;
    if (gid < NE) { g_count[gid] = 0; g_cursor[gid] = 0; }
}

// ---------------- kernel 1: gating (warp per token) ----------------
__global__ void __launch_bounds__(256) gate_kernel(
    const float* __restrict__ x, const float* __restrict__ gw, const float* __restrict__ gb)
{
    const int warp = (blockIdx.x * blockDim.x + threadIdx.x) >> 5;
    const int lane = threadIdx.x & 31;
    if (warp >= TOKENS) return;

    const float* xr = x + (size_t)warp * DM;
    float acc[NE];
#pragma unroll
    for (int e = 0; e < NE; e++) acc[e] = 0.f;
    for (int d = lane; d < DM; d += 32) {
        float xv = xr[d];
        const float4 g0 = *(const float4*)(gw + (size_t)d * NE);
        const float4 g1 = *(const float4*)(gw + (size_t)d * NE + 4);
        acc[0] += xv * g0.x;  acc[1] += xv * g0.y;
        acc[2] += xv * g0.z;  acc[3] += xv * g0.w;
        acc[4] += xv * g1.x;  acc[5] += xv * g1.y;
        acc[6] += xv * g1.z;  acc[7] += xv * g1.w;
    }
#pragma unroll
    for (int e = 0; e < NE; e++) {
#pragma unroll
        for (int off = 16; off; off >>= 1)
            acc[e] += __shfl_xor_sync(0xffffffffu, acc[e], off);
    }
    if (lane == 0) {
        float m = -1e30f;
#pragma unroll
        for (int e = 0; e < NE; e++) { acc[e] += gb[e]; m = fmaxf(m, acc[e]); }
        float s = 0.f;
#pragma unroll
        for (int e = 0; e < NE; e++) { acc[e] = __expf(acc[e] - m); s += acc[e]; }
        const float inv = 1.f / s;
        int i1 = 0; float p1 = acc[0];
#pragma unroll
        for (int e = 1; e < NE; e++) if (acc[e] > p1) { p1 = acc[e]; i1 = e; }
        int i2 = -1; float p2 = -1.f;
#pragma unroll
        for (int e = 0; e < NE; e++) if (e != i1 && acc[e] > p2) { p2 = acc[e]; i2 = e; }
        g_tope[2 * warp + 0] = i1;  g_topp[2 * warp + 0] = p1 * inv;
        g_tope[2 * warp + 1] = i2;  g_topp[2 * warp + 1] = p2 * inv;
        atomicAdd(&g_count[i1], 1);
        atomicAdd(&g_count[i2], 1);
    }
}

// ---------------- kernel 2: scan + padded mtile tables ----------------
__global__ void scan_kernel() {
    int o = 0, m = 0;
    for (int e = 0; e < NE; e++) {
        g_offpad[e] = o;
        const int c = g_count[e];
        const int nt = (c + 127) >> 7;
        for (int t = 0; t < nt; t++) {
            g_mt_e[m] = e;
            g_mt_valid[m] = min(128, c - t * 128);
            m++;
        }
        o += nt * 128;
    }
    g_nmt = m;
}

// ---------------- kernel 3: scatter tokens into padded expert groups ----------------
__global__ void scatter_kernel() {
    const int t = blockIdx.x * blockDim.x + threadIdx.x;
    if (t >= TOKENS) return;
#pragma unroll
    for (int k = 0; k < 2; k++) {
        const int e = g_tope[2 * t + k];
        const float p = g_topp[2 * t + k];
        const int pos = g_offpad[e] + atomicAdd(&g_cursor[e], 1);
        g_tok_pad[pos] = t;
        g_gw_pad[pos] = p;
    }
}

// ---------------- pregather x -> fragment-linear tiled A1 hi/lo ----------------
// Tile block = 8 KB = 512 fragments of 16 B. Fragment f: lane = f&31, w = f>>5,
// ks = w&1 (k16 step), mi = (w>>1)&3 (m16 idx), wm = w>>3 (warpM half).
// Fragment halves (mma.m16n8k16 A): h0,h1 = row g cols k0,k0+1; h2,h3 = row g+8;
// h4..h7 = same rows, cols k0+8,k0+9.
__global__ void __launch_bounds__(256) pregather_x(const float* __restrict__ x) {
    const int mt = blockIdx.y;
    if (mt >= g_nmt) return;
    const int kc = blockIdx.x;
    const size_t blk = ((size_t)mt * KCH1 + kc) * 4096;

    for (int f = threadIdx.x; f < 512; f += 256) {
        const int lane = f & 31, w = f >> 5;
        const int ks = w & 1, mi = (w >> 1) & 3, wm = w >> 3;
        const int g = lane >> 2, t = lane & 3;
        const int k0 = kc * 32 + ks * 16 + 2 * t;
        H8 hh, ll;
#pragma unroll
        for (int rr = 0; rr < 2; rr++) {
            const int slot = mt * 128 + wm * 64 + mi * 16 + g + rr * 8;
            const int tok = g_tok_pad[slot];
            float v0 = 0.f, v1 = 0.f, v2 = 0.f, v3 = 0.f;
            if (tok >= 0) {
                const float2 p0 = *(const float2*)(x + (size_t)tok * DM + k0);
                const float2 p1 = *(const float2*)(x + (size_t)tok * DM + k0 + 8);
                v0 = p0.x; v1 = p0.y; v2 = p1.x; v3 = p1.y;
            }
            hh.h[rr * 2 + 0] = __float2half_rn(v0);
            ll.h[rr * 2 + 0] = __float2half_rn(v0 - __half2float(hh.h[rr * 2 + 0]));
            hh.h[rr * 2 + 1] = __float2half_rn(v1);
            ll.h[rr * 2 + 1] = __float2half_rn(v1 - __half2float(hh.h[rr * 2 + 1]));
            hh.h[4 + rr * 2 + 0] = __float2half_rn(v2);
            ll.h[4 + rr * 2 + 0] = __float2half_rn(v2 - __half2float(hh.h[4 + rr * 2 + 0]));
            hh.h[4 + rr * 2 + 1] = __float2half_rn(v3);
            ll.h[4 + rr * 2 + 1] = __float2half_rn(v3 - __half2float(hh.h[4 + rr * 2 + 1]));
        }
        *(uint4*)(g_A1hi + blk + (size_t)f * 8) = *(uint4*)&hh;
        *(uint4*)(g_A1lo + blk + (size_t)f * 8) = *(uint4*)&ll;
    }
}

// ---------------- weight tilers: [E][K][N] -> fragment-linear B blocks hi/lo ----------------
// B fragment f = lane + 32*(ks + 2*np + 4*wn); halves: sub 0 = n8 col 2*np,
// sub 1 = n8 col 2*np+1; each sub = B[kb,n],B[kb+1,n],B[kb+8,n],B[kb+9,n].
__global__ void __launch_bounds__(256) tile_w1(
    const float* __restrict__ w, __half* __restrict__ bhi, __half* __restrict__ blo)
{
    const int e = blockIdx.z, nt = blockIdx.y, kc = blockIdx.x;
    const size_t blk = (((size_t)e * NT1 + nt) * KCH1 + kc) * 4096;
    const float* we = w + (size_t)e * DM * DFF;

    for (int f = threadIdx.x; f < 512; f += 256) {
        const int lane = f & 31, wi = f >> 5;
        const int ks = wi & 1, np = (wi >> 1) & 1, wn = wi >> 2;
        const int g = lane >> 2, t = lane & 3;
        const int kb = kc * 32 + ks * 16 + 2 * t;
        H8 hh, ll;
#pragma unroll
        for (int sub = 0; sub < 2; sub++) {
            const int n = nt * 128 + wn * 32 + (2 * np + sub) * 8 + g;
            const int kk[4] = { kb, kb + 1, kb + 8, kb + 9 };
#pragma unroll
            for (int q = 0; q < 4; q++) {
                const float v = we[(size_t)kk[q] * DFF + n];
                const __half h = __float2half_rn(v);
                hh.h[sub * 4 + q] = h;
                ll.h[sub * 4 + q] = __float2half_rn(v - __half2float(h));
            }
        }
        *(uint4*)(bhi + blk + (size_t)f * 8) = *(uint4*)&hh;
        *(uint4*)(blo + blk + (size_t)f * 8) = *(uint4*)&ll;
    }
}
__global__ void __launch_bounds__(256) tile_w2(
    const float* __restrict__ w, __half* __restrict__ bhi, __half* __restrict__ blo)
{
    const int e = blockIdx.z, nt = blockIdx.y, kc = blockIdx.x;
    const size_t blk = (((size_t)e * NT2 + nt) * KCH2 + kc) * 4096;
    const float* we = w + (size_t)e * DFF * DM;

    for (int f = threadIdx.x; f < 512; f += 256) {
        const int lane = f & 31, wi = f >> 5;
        const int ks = wi & 1, np = (wi >> 1) & 1, wn = wi >> 2;
        const int g = lane >> 2, t = lane & 3;
        const int kb = kc * 32 + ks * 16 + 2 * t;
        H8 hh, ll;
#pragma unroll
        for (int sub = 0; sub < 2; sub++) {
            const int n = nt * 128 + wn * 32 + (2 * np + sub) * 8 + g;
            const int kk[4] = { kb, kb + 1, kb + 8, kb + 9 };
#pragma unroll
            for (int q = 0; q < 4; q++) {
                const float v = we[(size_t)kk[q] * DM + n];
                const __half h = __float2half_rn(v);
                hh.h[sub * 4 + q] = h;
                ll.h[sub * 4 + q] = __float2half_rn(v - __half2float(h));
            }
        }
        *(uint4*)(bhi + blk + (size_t)f * 8) = *(uint4*)&hh;
        *(uint4*)(blo + blk + (size_t)f * 8) = *(uint4*)&ll;
    }
}

// ---------------- pipelined fragment GEMM: bulk-copy + mma.sync, 3-term emulation ----------------
template<int KCH, int NT, bool IS_G1>
__global__ void __launch_bounds__(256, 1) moe_gemm(
    const __half* __restrict__ Ahi, const __half* __restrict__ Alo,
    const __half* __restrict__ Bhi, const __half* __restrict__ Blo,
    const float* __restrict__ bias,
    __half* __restrict__ oHhi, __half* __restrict__ oHlo,
    float* __restrict__ out)
{
    const int mt = blockIdx.y;
    if (mt >= g_nmt) return;
    const int nt = blockIdx.x;
    const int e = g_mt_e[mt];
    const int valid = g_mt_valid[mt];

    extern __shared__ __align__(128) char smem[];
    const uint32_t SB = smem_u32(smem);
    const uint32_t FULLB  = SB + STAGES * STAGE_B;
    const uint32_t EMPTYB = FULLB + 8 * STAGES;

    const int tid = threadIdx.x;
    const int warp = tid >> 5;
    const int lane = tid & 31;

    if (tid == 0) {
#pragma unroll
        for (int s = 0; s < STAGES; s++) {
            MBAR_INIT(FULLB + 8 * s, 1);
            MBAR_INIT(EMPTYB + 8 * s, 8);
        }
    }
    __syncthreads();

    const char* abase  = (const char*)Ahi + ((size_t)mt * KCH) * 8192;
    const char* albase = (const char*)Alo + ((size_t)mt * KCH) * 8192;
    const char* bbase  = (const char*)Bhi + (((size_t)e * NT + nt) * KCH) * 8192;
    const char* blbase = (const char*)Blo + (((size_t)e * NT + nt) * KCH) * 8192;

    // prologue: fill first 2 stages
    if (tid == 0) {
#pragma unroll
        for (int c = 0; c < 2; c++) {
            const uint32_t sa = SB + c * STAGE_B;
            MBAR_EXPECT_TX(FULLB + 8 * c, STAGE_B);
            bulk_g2s(sa,         abase  + (size_t)c * 8192, 8192, FULLB + 8 * c);
            bulk_g2s(sa + 8192,  albase + (size_t)c * 8192, 8192, FULLB + 8 * c);
            bulk_g2s(sa + 16384, bbase  + (size_t)c * 8192, 8192, FULLB + 8 * c);
            bulk_g2s(sa + 24576, blbase + (size_t)c * 8192, 8192, FULLB + 8 * c);
        }
    }

    const int warpM = warp & 1, warpN = warp >> 1;
    uint32_t aoff[4][2], boff[2][2];
#pragma unroll
    for (int mi = 0; mi < 4; mi++)
#pragma unroll
        for (int ks = 0; ks < 2; ks++)
            aoff[mi][ks] = (uint32_t)((lane + 32 * (ks + 2 * mi + 8 * warpM)) * 16);
#pragma unroll
    for (int np = 0; np < 2; np++)
#pragma unroll
        for (int ks = 0; ks < 2; ks++)
            boff[np][ks] = (uint32_t)((lane + 32 * (ks + 2 * np + 4 * warpN)) * 16);

    float acc[4][4][4];
#pragma unroll
    for (int i = 0; i < 4; i++)
#pragma unroll
        for (int j = 0; j < 4; j++)
#pragma unroll
            for (int k = 0; k < 4; k++) acc[i][j][k] = 0.f;

    // Producer cursor: first wait on a FRESH empty barrier must use parity 1
    // (fresh barrier is in phase 0, so wait(1) passes immediately). This was
    // the R6 deadlock: pph=0 waited on EMPTY[2] phase-0 completion that could
    // only happen after the very chunk being loaded was consumed.
    int pst = 2, pph = 1;
    int cst = 0, cph = 0;

    for (int c = 0; c < KCH; c++) {
        mbar_wait(FULLB + 8 * cst, cph);
        const uint32_t sa = SB + cst * STAGE_B;

#pragma unroll
        for (int ks = 0; ks < 2; ks++) {
            uint4 ah[4], al[4], bh[2], bl[2];
#pragma unroll
            for (int mi = 0; mi < 4; mi++) {
                ah[mi] = lds128(sa + aoff[mi][ks]);
                al[mi] = lds128(sa + 8192 + aoff[mi][ks]);
            }
#pragma unroll
            for (int np = 0; np < 2; np++) {
                bh[np] = lds128(sa + 16384 + boff[np][ks]);
                bl[np] = lds128(sa + 24576 + boff[np][ks]);
            }
#pragma unroll
            for (int mi = 0; mi < 4; mi++) {
#pragma unroll
                for (int np = 0; np < 2; np++) {
                    mma_f16(acc[mi][2 * np],     (uint32_t*)&ah[mi], bh[np].x, bh[np].y);
                    mma_f16(acc[mi][2 * np + 1], (uint32_t*)&ah[mi], bh[np].z, bh[np].w);
                    mma_f16(acc[mi][2 * np],     (uint32_t*)&ah[mi], bl[np].x, bl[np].y);
                    mma_f16(acc[mi][2 * np + 1], (uint32_t*)&ah[mi], bl[np].z, bl[np].w);
                    mma_f16(acc[mi][2 * np],     (uint32_t*)&al[mi], bh[np].x, bh[np].y);
                    mma_f16(acc[mi][2 * np + 1], (uint32_t*)&al[mi], bh[np].z, bh[np].w);
                }
            }
        }
        __syncwarp();
        if (lane == 0) MBAR_ARRIVE(EMPTYB + 8 * cst);

        if (tid == 0 && c + 2 < KCH) {
            mbar_wait_relaxed(EMPTYB + 8 * pst, pph);
            const uint32_t da = SB + pst * STAGE_B;
            MBAR_EXPECT_TX(FULLB + 8 * pst, STAGE_B);
            bulk_g2s(da,         abase  + (size_t)(c + 2) * 8192, 8192, FULLB + 8 * pst);
            bulk_g2s(da + 8192,  albase + (size_t)(c + 2) * 8192, 8192, FULLB + 8 * pst);
            bulk_g2s(da + 16384, bbase  + (size_t)(c + 2) * 8192, 8192, FULLB + 8 * pst);
            bulk_g2s(da + 24576, blbase + (size_t)(c + 2) * 8192, 8192, FULLB + 8 * pst);
            if (++pst == STAGES) { pst = 0; pph ^= 1; }
        }
        if (++cst == STAGES) { cst = 0; cph ^= 1; }
    }

    // ---------------- epilogue ----------------
    const int g = lane >> 2, t = lane & 3;
    if (IS_G1) {
        // Write H directly in G2's A-fragment-linear layout (bias + SiLU + hi/lo split).
#pragma unroll
        for (int ni = 0; ni < 4; ni++) {
            const int col = nt * 128 + warpN * 32 + ni * 8 + 2 * t;
            const float b0 = bias[(size_t)e * DFF + col];
            const float b1 = bias[(size_t)e * DFF + col + 1];
            const int kcH = nt * 4 + warpN;
            const int ks2 = ni >> 1;
#pragma unroll
            for (int mi = 0; mi < 4; mi++) {
                const int r0 = warpM * 64 + mi * 16 + g;
                float v0 = acc[mi][ni][0] + b0, v1 = acc[mi][ni][1] + b1;
                float v2 = acc[mi][ni][2] + b0, v3 = acc[mi][ni][3] + b1;
                v0 = v0 / (1.f + __expf(-v0));
                v1 = v1 / (1.f + __expf(-v1));
                v2 = v2 / (1.f + __expf(-v2));
                v3 = v3 / (1.f + __expf(-v3));
                if (r0 >= valid)     { v0 = 0.f; v1 = 0.f; }
                if (r0 + 8 >= valid) { v2 = 0.f; v3 = 0.f; }
                const __half h0 = __float2half_rn(v0), h1 = __float2half_rn(v1);
                const __half h2 = __float2half_rn(v2), h3 = __float2half_rn(v3);
                const __half l0 = __float2half_rn(v0 - __half2float(h0));
                const __half l1 = __float2half_rn(v1 - __half2float(h1));
                const __half l2 = __float2half_rn(v2 - __half2float(h2));
                const __half l3 = __float2half_rn(v3 - __half2float(h3));
                const int fA = lane + 32 * (ks2 + 2 * mi + 8 * warpM);
                const size_t off = ((size_t)mt * (DFF / 32) + kcH) * 4096 +
                                   (size_t)fA * 8 + (size_t)(ni & 1) * 4;
                uint2 sh, sl;
                sh.x = pack_h2(h0, h1);  sh.y = pack_h2(h2, h3);
                sl.x = pack_h2(l0, l1);  sl.y = pack_h2(l2, l3);
                *(uint2*)(oHhi + off) = sh;
                *(uint2*)(oHlo + off) = sl;
            }
        }
    } else {
        float bb0[4], bb1[4];
#pragma unroll
        for (int ni = 0; ni < 4; ni++) {
            const int col = nt * 128 + warpN * 32 + ni * 8 + 2 * t;
            bb0[ni] = bias[(size_t)e * DM + col];
            bb1[ni] = bias[(size_t)e * DM + col + 1];
        }
#pragma unroll
        for (int mi = 0; mi < 4; mi++) {
            const int r0 = warpM * 64 + mi * 16 + g;
            const int slot0 = mt * 128 + r0;
            const int slot1 = slot0 + 8;
            const bool ok0 = r0 < valid;
            const bool ok1 = (r0 + 8) < valid;
            const int tok0 = ok0 ? g_tok_pad[slot0] : 0;
            const int tok1 = ok1 ? g_tok_pad[slot1] : 0;
            const float gw0 = ok0 ? g_gw_pad[slot0] : 0.f;
            const float gw1 = ok1 ? g_gw_pad[slot1] : 0.f;
#pragma unroll
            for (int ni = 0; ni < 4; ni++) {
                const int col = nt * 128 + warpN * 32 + ni * 8 + 2 * t;
                if (ok0) {
                    float* op = out + (size_t)tok0 * DM + col;
                    atomicAdd(op,     gw0 * (acc[mi][ni][0] + bb0[ni]));
                    atomicAdd(op + 1, gw0 * (acc[mi][ni][1] + bb1[ni]));
                }
                if (ok1) {
                    float* op = out + (size_t)tok1 * DM + col;
                    atomicAdd(op,     gw1 * (acc[mi][ni][2] + bb0[ni]));
                    atomicAdd(op + 1, gw1 * (acc[mi][ni][3] + bb1[ni]));
                }
            }
        }
    }
}

// ---------------- launch ----------------
extern "C" void kernel_launch(void* const* d_in, const int* in_sizes, int n_in,
                              void* d_out, int out_size)
{
    const float* x      = (const float*)d_in[0];
    const float* gate_w = (const float*)d_in[1];
    const float* gate_b = (const float*)d_in[2];
    const float* w1     = (const float*)d_in[3];
    const float* b1     = (const float*)d_in[4];
    const float* w2     = (const float*)d_in[5];
    const float* b2     = (const float*)d_in[6];
    float* out = (float*)d_out;

    cudaFuncSetAttribute(moe_gemm<KCH1, NT1, true>,
                         cudaFuncAttributeMaxDynamicSharedMemorySize, SMEM_DYN);
    cudaFuncSetAttribute(moe_gemm<KCH2, NT2, false>,
                         cudaFuncAttributeMaxDynamicSharedMemorySize, SMEM_DYN);

    __half *a1hi, *a1lo, *b1hi, *b1lo, *hhi, *hlo, *b2hi, *b2lo;
    cudaGetSymbolAddress((void**)&a1hi, g_A1hi);
    cudaGetSymbolAddress((void**)&a1lo, g_A1lo);
    cudaGetSymbolAddress((void**)&b1hi, g_B1hi);
    cudaGetSymbolAddress((void**)&b1lo, g_B1lo);
    cudaGetSymbolAddress((void**)&hhi,  g_Hhi);
    cudaGetSymbolAddress((void**)&hlo,  g_Hlo);
    cudaGetSymbolAddress((void**)&b2hi, g_B2hi);
    cudaGetSymbolAddress((void**)&b2lo, g_B2lo);

    zero_kernel<<<2048, 256>>>((float4*)out);
    gate_kernel<<<TOKENS / 8, 256>>>(x, gate_w, gate_b);
    scan_kernel<<<1, 1>>>();
    scatter_kernel<<<TOKENS / 256, 256>>>();

    pregather_x<<<dim3(KCH1, MT_MAX), 256>>>(x);
    tile_w1<<<dim3(KCH1, NT1, NE), 256>>>(w1, b1hi, b1lo);
    tile_w2<<<dim3(KCH2, NT2, NE), 256>>>(w2, b2hi, b2lo);

    moe_gemm<KCH1, NT1, true><<<dim3(NT1, MT_MAX), 256, SMEM_DYN>>>(
        a1hi, a1lo, b1hi, b1lo, b1, hhi, hlo, nullptr);
    moe_gemm<KCH2, NT2, false><<<dim3(NT2, MT_MAX), 256, SMEM_DYN>>>(
        hhi, hlo, b2hi, b2lo, b2, nullptr, nullptr, out);
}

// round 8
// speedup vs baseline: 3.3886x; 1.0695x over previous
#include <cuda_runtime.h>
#include <cuda_fp16.h>
#include <cstdint>
#include <math.h>

#define TOKENS   8192
#define DM       1024
#define DFF      4096
#define NE       8
#define NSLOTS   (TOKENS * 2)

#define MT_MAX   (NSLOTS / 128 + NE)   // 136 padded m-tiles max
#define PADSLOTS (MT_MAX * 128)        // 17408
#define KCH1     (DM / 32)             // 32 k-chunks for GEMM1
#define KCH2     (DFF / 32)            // 128 k-chunks for GEMM2
#define NT1      (DFF / 256)           // 16 n-tiles GEMM1 (N tile = 256)
#define NT2      (DM / 256)            // 4  n-tiles GEMM2

#define STAGES   3
// per stage: A_hi 8KB + A_lo 8KB + B_hi 16KB + B_lo 16KB
#define STAGE_B  49152
#define SMEM_DYN (STAGES * STAGE_B + 64)

// ---------------- static device scratch (fragment-linear tiled) ----------------
__device__ __align__(16) __half g_A1hi[(size_t)PADSLOTS * DM];
__device__ __align__(16) __half g_A1lo[(size_t)PADSLOTS * DM];
__device__ __align__(16) __half g_B1hi[(size_t)NE * DFF * DM];
__device__ __align__(16) __half g_B1lo[(size_t)NE * DFF * DM];
__device__ __align__(16) __half g_Hhi[(size_t)PADSLOTS * DFF];
__device__ __align__(16) __half g_Hlo[(size_t)PADSLOTS * DFF];
__device__ __align__(16) __half g_B2hi[(size_t)NE * DM * DFF];
__device__ __align__(16) __half g_B2lo[(size_t)NE * DM * DFF];

__device__ int   g_tope[NSLOTS];
__device__ float g_topp[NSLOTS];
__device__ int   g_tok_pad[PADSLOTS];
__device__ float g_gw_pad[PADSLOTS];
__device__ int   g_count[NE];
__device__ int   g_cursor[NE];
__device__ int   g_offpad[NE];
__device__ int   g_mt_e[MT_MAX];
__device__ int   g_mt_valid[MT_MAX];
__device__ int   g_nmt;

struct alignas(16) H8 { __half h[8]; };

// ---------------- PTX helpers ----------------
__device__ __forceinline__ uint32_t smem_u32(const void* p) {
    uint32_t a;
    asm("{ .reg .u64 t; cvta.to.shared.u64 t, %1; cvt.u32.u64 %0, t; }" : "=r"(a) : "l"(p));
    return a;
}
#define MBAR_INIT(a, c) \
    asm volatile("mbarrier.init.shared.b64 [%0], %1;" :: "r"(a), "r"((uint32_t)(c)) : "memory")
#define MBAR_EXPECT_TX(a, b) \
    asm volatile("mbarrier.arrive.expect_tx.shared.b64 _, [%0], %1;" :: "r"(a), "r"((uint32_t)(b)) : "memory")
#define MBAR_ARRIVE(a) \
    asm volatile("mbarrier.arrive.shared.b64 _, [%0];" :: "r"(a) : "memory")

__device__ __forceinline__ void mbar_wait(uint32_t mbar, uint32_t parity) {
    asm volatile(
        "{\n\t.reg .pred P;\n"
        "WL_%=:\n\t"
        "mbarrier.try_wait.parity.acquire.cta.shared::cta.b64 P, [%0], %1, 0x989680;\n\t"
        "@P bra.uni WD_%=;\n\t"
        "bra.uni WL_%=;\n"
        "WD_%=:\n\t}"
        :: "r"(mbar), "r"(parity) : "memory");
}
__device__ __forceinline__ void mbar_wait_relaxed(uint32_t mbar, uint32_t parity) {
    asm volatile(
        "{\n\t.reg .pred P;\n"
        "WL_%=:\n\t"
        "mbarrier.try_wait.parity.relaxed.cta.shared::cta.b64 P, [%0], %1, 0x989680;\n\t"
        "@P bra.uni WD_%=;\n\t"
        "bra.uni WL_%=;\n"
        "WD_%=:\n\t}"
        :: "r"(mbar), "r"(parity) : "memory");
}
__device__ __forceinline__ void bulk_g2s(uint32_t dst, const void* src, uint32_t bytes, uint32_t mbar) {
    asm volatile(
        "cp.async.bulk.shared::cluster.global.mbarrier::complete_tx::bytes [%0], [%1], %2, [%3];"
        :: "r"(dst), "l"(src), "r"(bytes), "r"(mbar) : "memory");
}
__device__ __forceinline__ uint4 lds128(uint32_t a) {
    uint4 v;
    asm volatile("ld.shared.v4.u32 {%0,%1,%2,%3}, [%4];"
                 : "=r"(v.x), "=r"(v.y), "=r"(v.z), "=r"(v.w) : "r"(a));
    return v;
}
__device__ __forceinline__ void mma_f16(float* c, const uint32_t* a, uint32_t b0, uint32_t b1) {
    asm volatile(
        "mma.sync.aligned.m16n8k16.row.col.f32.f16.f16.f32 "
        "{%0,%1,%2,%3}, {%4,%5,%6,%7}, {%8,%9}, {%0,%1,%2,%3};"
        : "+f"(c[0]), "+f"(c[1]), "+f"(c[2]), "+f"(c[3])
        : "r"(a[0]), "r"(a[1]), "r"(a[2]), "r"(a[3]), "r"(b0), "r"(b1));
}
__device__ __forceinline__ uint32_t pack_h2(__half a, __half b) {
    __half2 h = __halves2half2(a, b);
    return *(uint32_t*)&h;
}

// ---------------- kernel 0: zero output + routing state ----------------
__global__ void zero_kernel(float4* __restrict__ out) {
    const int gid = blockIdx.x * blockDim.x + threadIdx.x;
    const int stride = gridDim.x * blockDim.x;
    const int n4 = TOKENS * DM / 4;
    float4 z = make_float4(0.f, 0.f, 0.f, 0.f);
    for (int i = gid; i < n4; i += stride) out[i] = z;
    if (gid < PADSLOTS) g_tok_pad[gid] = -1;
    if (gid < NE) { g_count[gid] = 0; g_cursor[gid] = 0; }
}

// ---------------- kernel 1: gating (warp per token) ----------------
__global__ void __launch_bounds__(256) gate_kernel(
    const float* __restrict__ x, const float* __restrict__ gw, const float* __restrict__ gb)
{
    const int warp = (blockIdx.x * blockDim.x + threadIdx.x) >> 5;
    const int lane = threadIdx.x & 31;
    if (warp >= TOKENS) return;

    const float* xr = x + (size_t)warp * DM;
    float acc[NE];
#pragma unroll
    for (int e = 0; e < NE; e++) acc[e] = 0.f;
    for (int d = lane; d < DM; d += 32) {
        float xv = xr[d];
        const float4 g0 = *(const float4*)(gw + (size_t)d * NE);
        const float4 g1 = *(const float4*)(gw + (size_t)d * NE + 4);
        acc[0] += xv * g0.x;  acc[1] += xv * g0.y;
        acc[2] += xv * g0.z;  acc[3] += xv * g0.w;
        acc[4] += xv * g1.x;  acc[5] += xv * g1.y;
        acc[6] += xv * g1.z;  acc[7] += xv * g1.w;
    }
#pragma unroll
    for (int e = 0; e < NE; e++) {
#pragma unroll
        for (int off = 16; off; off >>= 1)
            acc[e] += __shfl_xor_sync(0xffffffffu, acc[e], off);
    }
    if (lane == 0) {
        float m = -1e30f;
#pragma unroll
        for (int e = 0; e < NE; e++) { acc[e] += gb[e]; m = fmaxf(m, acc[e]); }
        float s = 0.f;
#pragma unroll
        for (int e = 0; e < NE; e++) { acc[e] = __expf(acc[e] - m); s += acc[e]; }
        const float inv = 1.f / s;
        int i1 = 0; float p1 = acc[0];
#pragma unroll
        for (int e = 1; e < NE; e++) if (acc[e] > p1) { p1 = acc[e]; i1 = e; }
        int i2 = -1; float p2 = -1.f;
#pragma unroll
        for (int e = 0; e < NE; e++) if (e != i1 && acc[e] > p2) { p2 = acc[e]; i2 = e; }
        g_tope[2 * warp + 0] = i1;  g_topp[2 * warp + 0] = p1 * inv;
        g_tope[2 * warp + 1] = i2;  g_topp[2 * warp + 1] = p2 * inv;
        atomicAdd(&g_count[i1], 1);
        atomicAdd(&g_count[i2], 1);
    }
}

// ---------------- kernel 2: scan + padded mtile tables ----------------
__global__ void scan_kernel() {
    int o = 0, m = 0;
    for (int e = 0; e < NE; e++) {
        g_offpad[e] = o;
        const int c = g_count[e];
        const int nt = (c + 127) >> 7;
        for (int t = 0; t < nt; t++) {
            g_mt_e[m] = e;
            g_mt_valid[m] = min(128, c - t * 128);
            m++;
        }
        o += nt * 128;
    }
    g_nmt = m;
}

// ---------------- kernel 3: scatter tokens into padded expert groups ----------------
__global__ void scatter_kernel() {
    const int t = blockIdx.x * blockDim.x + threadIdx.x;
    if (t >= TOKENS) return;
#pragma unroll
    for (int k = 0; k < 2; k++) {
        const int e = g_tope[2 * t + k];
        const float p = g_topp[2 * t + k];
        const int pos = g_offpad[e] + atomicAdd(&g_cursor[e], 1);
        g_tok_pad[pos] = t;
        g_gw_pad[pos] = p;
    }
}

// ---------------- pregather x -> fragment-linear tiled A1 hi/lo ----------------
// A tile block = 8 KB = 512 fragments of 16 B. Fragment f: lane = f&31, w = f>>5,
// ks = w&1 (k16 step), mi = (w>>1)&3 (m16 idx), wm = w>>3 (warpM, 0..1).
// Fragment halves (mma.m16n8k16 A): h0,h1 = row g cols k0,k0+1; h2,h3 = row g+8;
// h4..h7 = same rows, cols k0+8,k0+9.
__global__ void __launch_bounds__(256) pregather_x(const float* __restrict__ x) {
    const int mt = blockIdx.y;
    if (mt >= g_nmt) return;
    const int kc = blockIdx.x;
    const size_t blk = ((size_t)mt * KCH1 + kc) * 4096;

    for (int f = threadIdx.x; f < 512; f += 256) {
        const int lane = f & 31, w = f >> 5;
        const int ks = w & 1, mi = (w >> 1) & 3, wm = w >> 3;
        const int g = lane >> 2, t = lane & 3;
        const int k0 = kc * 32 + ks * 16 + 2 * t;
        H8 hh, ll;
#pragma unroll
        for (int rr = 0; rr < 2; rr++) {
            const int slot = mt * 128 + wm * 64 + mi * 16 + g + rr * 8;
            const int tok = g_tok_pad[slot];
            float v0 = 0.f, v1 = 0.f, v2 = 0.f, v3 = 0.f;
            if (tok >= 0) {
                const float2 p0 = *(const float2*)(x + (size_t)tok * DM + k0);
                const float2 p1 = *(const float2*)(x + (size_t)tok * DM + k0 + 8);
                v0 = p0.x; v1 = p0.y; v2 = p1.x; v3 = p1.y;
            }
            hh.h[rr * 2 + 0] = __float2half_rn(v0);
            ll.h[rr * 2 + 0] = __float2half_rn(v0 - __half2float(hh.h[rr * 2 + 0]));
            hh.h[rr * 2 + 1] = __float2half_rn(v1);
            ll.h[rr * 2 + 1] = __float2half_rn(v1 - __half2float(hh.h[rr * 2 + 1]));
            hh.h[4 + rr * 2 + 0] = __float2half_rn(v2);
            ll.h[4 + rr * 2 + 0] = __float2half_rn(v2 - __half2float(hh.h[4 + rr * 2 + 0]));
            hh.h[4 + rr * 2 + 1] = __float2half_rn(v3);
            ll.h[4 + rr * 2 + 1] = __float2half_rn(v3 - __half2float(hh.h[4 + rr * 2 + 1]));
        }
        *(uint4*)(g_A1hi + blk + (size_t)f * 8) = *(uint4*)&hh;
        *(uint4*)(g_A1lo + blk + (size_t)f * 8) = *(uint4*)&ll;
    }
}

// ---------------- weight tilers: [E][K][N] -> fragment-linear B blocks (N tile 256) ----------
// B block = 16 KB = 1024 fragments. Fragment f = lane + 32*(ks + 2*np + 8*wn),
// np 0..3, wn 0..3 (warpN), ks 0..1. Halves: sub 0 = n8 col (wn*8 + 2*np),
// sub 1 = next n8; each sub = B[kb,n],B[kb+1,n],B[kb+8,n],B[kb+9,n], kb = kc*32+ks*16+2t.
template<int N, int NT, int KCH>
__global__ void __launch_bounds__(256) tile_w(
    const float* __restrict__ w, __half* __restrict__ bhi, __half* __restrict__ blo)
{
    const int e = blockIdx.z, nt = blockIdx.y, kc = blockIdx.x;
    const size_t blk = (((size_t)e * NT + nt) * KCH + kc) * 8192;
    const float* we = w + (size_t)e * (size_t)(N) * (NT == NT1 ? DM : DFF);
    const int K_LD = N;   // leading dim of [K][N] row = N

    for (int f = threadIdx.x; f < 1024; f += 256) {
        const int lane = f & 31, wi = f >> 5;
        const int ks = wi & 1, np = (wi >> 1) & 3, wn = wi >> 3;
        const int g = lane >> 2, t = lane & 3;
        const int kb = kc * 32 + ks * 16 + 2 * t;
        H8 hh, ll;
#pragma unroll
        for (int sub = 0; sub < 2; sub++) {
            const int n = nt * 256 + wn * 64 + (2 * np + sub) * 8 + g;
            const int kk[4] = { kb, kb + 1, kb + 8, kb + 9 };
#pragma unroll
            for (int q = 0; q < 4; q++) {
                const float v = we[(size_t)kk[q] * K_LD + n];
                const __half h = __float2half_rn(v);
                hh.h[sub * 4 + q] = h;
                ll.h[sub * 4 + q] = __float2half_rn(v - __half2float(h));
            }
        }
        *(uint4*)(bhi + blk + (size_t)f * 8) = *(uint4*)&hh;
        *(uint4*)(blo + blk + (size_t)f * 8) = *(uint4*)&ll;
    }
}

// ---------------- pipelined fragment GEMM: CTA 128x256, warp 64x64, 3-term emulation ------
template<int KCH, int NT, int NDIM, bool IS_G1>
__global__ void __launch_bounds__(256, 1) moe_gemm(
    const __half* __restrict__ Ahi, const __half* __restrict__ Alo,
    const __half* __restrict__ Bhi, const __half* __restrict__ Blo,
    const float* __restrict__ bias,
    __half* __restrict__ oHhi, __half* __restrict__ oHlo,
    float* __restrict__ out)
{
    const int mt = blockIdx.x;           // mt fastest -> in-flight CTAs share B (L2 reuse)
    if (mt >= g_nmt) return;
    const int nt = blockIdx.y;
    const int e = g_mt_e[mt];
    const int valid = g_mt_valid[mt];

    extern __shared__ __align__(128) char smem[];
    const uint32_t SB = smem_u32(smem);
    const uint32_t FULLB  = SB + STAGES * STAGE_B;
    const uint32_t EMPTYB = FULLB + 8 * STAGES;

    const int tid = threadIdx.x;
    const int warp = tid >> 5;
    const int lane = tid & 31;

    if (tid == 0) {
#pragma unroll
        for (int s = 0; s < STAGES; s++) {
            MBAR_INIT(FULLB + 8 * s, 1);
            MBAR_INIT(EMPTYB + 8 * s, 8);
        }
    }
    __syncthreads();

    const char* abase  = (const char*)Ahi + ((size_t)mt * KCH) * 8192;
    const char* albase = (const char*)Alo + ((size_t)mt * KCH) * 8192;
    const char* bbase  = (const char*)Bhi + (((size_t)e * NT + nt) * KCH) * 16384;
    const char* blbase = (const char*)Blo + (((size_t)e * NT + nt) * KCH) * 16384;

    // prologue: fill first 2 stages
    if (tid == 0) {
#pragma unroll
        for (int c = 0; c < 2; c++) {
            const uint32_t sa = SB + c * STAGE_B;
            MBAR_EXPECT_TX(FULLB + 8 * c, STAGE_B);
            bulk_g2s(sa,         abase  + (size_t)c * 8192,  8192,  FULLB + 8 * c);
            bulk_g2s(sa + 8192,  albase + (size_t)c * 8192,  8192,  FULLB + 8 * c);
            bulk_g2s(sa + 16384, bbase  + (size_t)c * 16384, 16384, FULLB + 8 * c);
            bulk_g2s(sa + 32768, blbase + (size_t)c * 16384, 16384, FULLB + 8 * c);
        }
    }

    const int warpM = warp & 1, warpN = warp >> 1;    // 2 x 4 warp grid, 64x64 tiles
    uint32_t aoff[4][2], boff[4][2];
#pragma unroll
    for (int mi = 0; mi < 4; mi++)
#pragma unroll
        for (int ks = 0; ks < 2; ks++)
            aoff[mi][ks] = (uint32_t)((lane + 32 * (ks + 2 * mi + 8 * warpM)) * 16);
#pragma unroll
    for (int np = 0; np < 4; np++)
#pragma unroll
        for (int ks = 0; ks < 2; ks++)
            boff[np][ks] = (uint32_t)((lane + 32 * (ks + 2 * np + 8 * warpN)) * 16);

    float acc[4][8][4];
#pragma unroll
    for (int i = 0; i < 4; i++)
#pragma unroll
        for (int j = 0; j < 8; j++)
#pragma unroll
            for (int k = 0; k < 4; k++) acc[i][j][k] = 0.f;

    // producer: first wait on fresh empty barrier uses parity 1 (passes immediately)
    int pst = 2, pph = 1;
    int cst = 0, cph = 0;

    for (int c = 0; c < KCH; c++) {
        mbar_wait(FULLB + 8 * cst, cph);
        const uint32_t sa = SB + cst * STAGE_B;

#pragma unroll
        for (int ks = 0; ks < 2; ks++) {
            uint4 bh[4], bl[4];
#pragma unroll
            for (int np = 0; np < 4; np++) {
                bh[np] = lds128(sa + 16384 + boff[np][ks]);
                bl[np] = lds128(sa + 32768 + boff[np][ks]);
            }
#pragma unroll
            for (int mi = 0; mi < 4; mi++) {
                const uint4 ah = lds128(sa + aoff[mi][ks]);
                const uint4 al = lds128(sa + 8192 + aoff[mi][ks]);
#pragma unroll
                for (int np = 0; np < 4; np++) {
                    mma_f16(acc[mi][2 * np],     (const uint32_t*)&ah, bh[np].x, bh[np].y);
                    mma_f16(acc[mi][2 * np + 1], (const uint32_t*)&ah, bh[np].z, bh[np].w);
                    mma_f16(acc[mi][2 * np],     (const uint32_t*)&ah, bl[np].x, bl[np].y);
                    mma_f16(acc[mi][2 * np + 1], (const uint32_t*)&ah, bl[np].z, bl[np].w);
                    mma_f16(acc[mi][2 * np],     (const uint32_t*)&al, bh[np].x, bh[np].y);
                    mma_f16(acc[mi][2 * np + 1], (const uint32_t*)&al, bh[np].z, bh[np].w);
                }
            }
        }
        __syncwarp();
        if (lane == 0) MBAR_ARRIVE(EMPTYB + 8 * cst);

        if (tid == 0 && c + 2 < KCH) {
            mbar_wait_relaxed(EMPTYB + 8 * pst, pph);
            const uint32_t da = SB + pst * STAGE_B;
            MBAR_EXPECT_TX(FULLB + 8 * pst, STAGE_B);
            bulk_g2s(da,         abase  + (size_t)(c + 2) * 8192,  8192,  FULLB + 8 * pst);
            bulk_g2s(da + 8192,  albase + (size_t)(c + 2) * 8192,  8192,  FULLB + 8 * pst);
            bulk_g2s(da + 16384, bbase  + (size_t)(c + 2) * 16384, 16384, FULLB + 8 * pst);
            bulk_g2s(da + 32768, blbase + (size_t)(c + 2) * 16384, 16384, FULLB + 8 * pst);
            if (++pst == STAGES) { pst = 0; pph ^= 1; }
        }
        if (++cst == STAGES) { cst = 0; cph ^= 1; }
    }

    // ---------------- epilogue ----------------
    const int g = lane >> 2, t = lane & 3;
    if (IS_G1) {
        // Write H in G2's A-fragment-linear layout (bias + SiLU + hi/lo split).
        // col = nt*256 + warpN*64 + n8*8 + 2t
        // kcH = nt*8 + warpN*2 + (n8>>2); ks2 = (n8>>1)&1; fragment half = n8&1.
#pragma unroll
        for (int n8 = 0; n8 < 8; n8++) {
            const int col = nt * 256 + warpN * 64 + n8 * 8 + 2 * t;
            const float b0 = bias[(size_t)e * NDIM + col];
            const float b1 = bias[(size_t)e * NDIM + col + 1];
            const int kcH = nt * 8 + warpN * 2 + (n8 >> 2);
            const int ks2 = (n8 >> 1) & 1;
#pragma unroll
            for (int mi = 0; mi < 4; mi++) {
                const int r0 = warpM * 64 + mi * 16 + g;
                float v0 = acc[mi][n8][0] + b0, v1 = acc[mi][n8][1] + b1;
                float v2 = acc[mi][n8][2] + b0, v3 = acc[mi][n8][3] + b1;
                v0 = v0 / (1.f + __expf(-v0));
                v1 = v1 / (1.f + __expf(-v1));
                v2 = v2 / (1.f + __expf(-v2));
                v3 = v3 / (1.f + __expf(-v3));
                if (r0 >= valid)     { v0 = 0.f; v1 = 0.f; }
                if (r0 + 8 >= valid) { v2 = 0.f; v3 = 0.f; }
                const __half h0 = __float2half_rn(v0), h1 = __float2half_rn(v1);
                const __half h2 = __float2half_rn(v2), h3 = __float2half_rn(v3);
                const __half l0 = __float2half_rn(v0 - __half2float(h0));
                const __half l1 = __float2half_rn(v1 - __half2float(h1));
                const __half l2 = __float2half_rn(v2 - __half2float(h2));
                const __half l3 = __float2half_rn(v3 - __half2float(h3));
                const int fA = lane + 32 * (ks2 + 2 * mi + 8 * warpM);
                const size_t off = ((size_t)mt * (DFF / 32) + kcH) * 4096 +
                                   (size_t)fA * 8 + (size_t)(n8 & 1) * 4;
                uint2 sh, sl;
                sh.x = pack_h2(h0, h1);  sh.y = pack_h2(h2, h3);
                sl.x = pack_h2(l0, l1);  sl.y = pack_h2(l2, l3);
                *(uint2*)(oHhi + off) = sh;
                *(uint2*)(oHlo + off) = sl;
            }
        }
    } else {
#pragma unroll
        for (int mi = 0; mi < 4; mi++) {
            const int r0 = warpM * 64 + mi * 16 + g;
            const int slot0 = mt * 128 + r0;
            const int slot1 = slot0 + 8;
            const bool ok0 = r0 < valid;
            const bool ok1 = (r0 + 8) < valid;
            const int tok0 = ok0 ? g_tok_pad[slot0] : 0;
            const int tok1 = ok1 ? g_tok_pad[slot1] : 0;
            const float gw0 = ok0 ? g_gw_pad[slot0] : 0.f;
            const float gw1 = ok1 ? g_gw_pad[slot1] : 0.f;
#pragma unroll
            for (int n8 = 0; n8 < 8; n8++) {
                const int col = nt * 256 + warpN * 64 + n8 * 8 + 2 * t;
                const float b0 = bias[(size_t)e * NDIM + col];
                const float b1 = bias[(size_t)e * NDIM + col + 1];
                if (ok0) {
                    float* op = out + (size_t)tok0 * DM + col;
                    atomicAdd(op,     gw0 * (acc[mi][n8][0] + b0));
                    atomicAdd(op + 1, gw0 * (acc[mi][n8][1] + b1));
                }
                if (ok1) {
                    float* op = out + (size_t)tok1 * DM + col;
                    atomicAdd(op,     gw1 * (acc[mi][n8][2] + b0));
                    atomicAdd(op + 1, gw1 * (acc[mi][n8][3] + b1));
                }
            }
        }
    }
}

// ---------------- launch ----------------
extern "C" void kernel_launch(void* const* d_in, const int* in_sizes, int n_in,
                              void* d_out, int out_size)
{
    const float* x      = (const float*)d_in[0];
    const float* gate_w = (const float*)d_in[1];
    const float* gate_b = (const float*)d_in[2];
    const float* w1     = (const float*)d_in[3];
    const float* b1     = (const float*)d_in[4];
    const float* w2     = (const float*)d_in[5];
    const float* b2     = (const float*)d_in[6];
    float* out = (float*)d_out;

    cudaFuncSetAttribute(moe_gemm<KCH1, NT1, DFF, true>,
                         cudaFuncAttributeMaxDynamicSharedMemorySize, SMEM_DYN);
    cudaFuncSetAttribute(moe_gemm<KCH2, NT2, DM, false>,
                         cudaFuncAttributeMaxDynamicSharedMemorySize, SMEM_DYN);

    __half *a1hi, *a1lo, *b1hi, *b1lo, *hhi, *hlo, *b2hi, *b2lo;
    cudaGetSymbolAddress((void**)&a1hi, g_A1hi);
    cudaGetSymbolAddress((void**)&a1lo, g_A1lo);
    cudaGetSymbolAddress((void**)&b1hi, g_B1hi);
    cudaGetSymbolAddress((void**)&b1lo, g_B1lo);
    cudaGetSymbolAddress((void**)&hhi,  g_Hhi);
    cudaGetSymbolAddress((void**)&hlo,  g_Hlo);
    cudaGetSymbolAddress((void**)&b2hi, g_B2hi);
    cudaGetSymbolAddress((void**)&b2lo, g_B2lo);

    zero_kernel<<<2048, 256>>>((float4*)out);
    gate_kernel<<<TOKENS / 8, 256>>>(x, gate_w, gate_b);
    scan_kernel<<<1, 1>>>();
    scatter_kernel<<<TOKENS / 256, 256>>>();

    pregather_x<<<dim3(KCH1, MT_MAX), 256>>>(x);
    // tile_w template param N is the weight's fast dim (DFF for w1, DM for w2)
    tile_w<DFF, NT1, KCH1><<<dim3(KCH1, NT1, NE), 256>>>(w1, b1hi, b1lo);
    tile_w<DM,  NT2, KCH2><<<dim3(KCH2, NT2, NE), 256>>>(w2, b2hi, b2lo);

    moe_gemm<KCH1, NT1, DFF, true><<<dim3(MT_MAX, NT1), 256, SMEM_DYN>>>(
        a1hi, a1lo, b1hi, b1lo, b1, hhi, hlo, nullptr);
    moe_gemm<KCH2, NT2, DM, false><<<dim3(MT_MAX, NT2), 256, SMEM_DYN>>>(
        hhi, hlo, b2hi, b2lo, b2, nullptr, nullptr, out);
}